// round 13
// baseline (speedup 1.0000x reference)
#include <cuda_runtime.h>
#include <cuda_fp16.h>
#include <cstdint>

#define MAX_N 50000
#define MAX_E 1600000
#define CH    128

// ---------------- scratch (static device globals) ---------------------------
__device__ int    g_cnt [MAX_N];
__device__ int    g_cur [MAX_N];
__device__ int    g_off [MAX_N + 1];
__device__ int    g_part[256];
__device__ float  g_dinv[MAX_N];
__device__ int2   g_edges[MAX_E];
__device__ float  g_h   [(size_t)MAX_N * CH];
__device__ __half g_hh  [(size_t)MAX_N * CH];   // fp16 mirror for edge gathers
__device__ float  g_out1[(size_t)MAX_N * CH];
// transposed + split weights: [N=128][K]
__device__ __half g_w1h[128 * 256];
__device__ __half g_w1l[128 * 256];
__device__ __half g_w2h[128 * 128];
__device__ __half g_w2l[128 * 128];

// ---------------- preprocessing ---------------------------------------------
__global__ void zero_cnt_kernel(int* cnt, int* cur, int n) {
    int i = blockIdx.x * blockDim.x + threadIdx.x;
    if (i < n) { cnt[i] = 0; cur[i] = 0; }
}

// vectorized degree count: 4 edges per thread
__global__ void count_kernel(const int* __restrict__ dst, int* cnt, int E) {
    int i = (blockIdx.x * blockDim.x + threadIdx.x) * 4;
    if (i + 3 < E) {
        int4 d = *(const int4*)(dst + i);
        atomicAdd(&cnt[d.x], 1);
        atomicAdd(&cnt[d.y], 1);
        atomicAdd(&cnt[d.z], 1);
        atomicAdd(&cnt[d.w], 1);
    } else {
        for (int j = i; j < E; j++) atomicAdd(&cnt[dst[j]], 1);
    }
}

__global__ void dinv_kernel(const int* __restrict__ cnt, float* dinv, int n) {
    int i = blockIdx.x * blockDim.x + threadIdx.x;
    if (i < n) dinv[i] = rsqrtf((float)cnt[i] + 1.0f);   // +1 self loop
}

__global__ void scan_part_kernel(const int* __restrict__ cnt, int* __restrict__ part, int n) {
    __shared__ int sh[256];
    int b = blockIdx.x, t = threadIdx.x;
    int base = b * 1024 + t * 4;
    int s = 0;
    #pragma unroll
    for (int j = 0; j < 4; j++) if (base + j < n) s += cnt[base + j];
    sh[t] = s;
    __syncthreads();
    for (int o = 128; o > 0; o >>= 1) {
        if (t < o) sh[t] += sh[t + o];
        __syncthreads();
    }
    if (t == 0) part[b] = sh[0];
}

__global__ void scan_tops_kernel(int* part, int nb) {
    __shared__ int sh[128];
    int t = threadIdx.x;
    int v = (t < nb) ? part[t] : 0;
    sh[t] = v;
    __syncthreads();
    for (int o = 1; o < 128; o <<= 1) {
        int add = (t >= o) ? sh[t - o] : 0;
        __syncthreads();
        sh[t] += add;
        __syncthreads();
    }
    if (t < nb) part[t] = sh[t] - v;   // exclusive
}

__global__ void scan_write_kernel(const int* __restrict__ cnt, const int* __restrict__ part,
                                  int* __restrict__ off, int n, int E) {
    __shared__ int sh[256];
    int b = blockIdx.x, t = threadIdx.x;
    int base = b * 1024 + t * 4;
    int c[4]; int s = 0;
    #pragma unroll
    for (int j = 0; j < 4; j++) {
        c[j] = (base + j < n) ? cnt[base + j] : 0;
        s += c[j];
    }
    int v = s;
    sh[t] = s;
    __syncthreads();
    for (int o = 1; o < 256; o <<= 1) {
        int add = (t >= o) ? sh[t - o] : 0;
        __syncthreads();
        sh[t] += add;
        __syncthreads();
    }
    int ex = sh[t] - v + part[b];
    #pragma unroll
    for (int j = 0; j < 4; j++) {
        if (base + j < n) { off[base + j] = ex; ex += c[j]; }
    }
    if (b == 0 && t == 0) off[n] = E;
}

__global__ void fill_kernel(const int* __restrict__ src, const int* __restrict__ dst,
                            const float* __restrict__ dinv,
                            const int* __restrict__ off, int* __restrict__ cur,
                            int2* __restrict__ edges, int E)
{
    int e = blockIdx.x * blockDim.x + threadIdx.x;
    if (e >= E) return;
    int s = src[e], d = dst[e];
    float w = dinv[s] * dinv[d];
    int pos = off[d] + atomicAdd(&cur[d], 1);
    edges[pos] = make_int2(s, __float_as_int(w));
}

// transpose + fp16-split W[K][128] -> Wh/Wl[128][K]
__global__ void wsplit_kernel(const float* __restrict__ W,
                              __half* __restrict__ Wh, __half* __restrict__ Wl, int K)
{
    int i = blockIdx.x * blockDim.x + threadIdx.x;
    if (i >= K * 128) return;
    int k = i >> 7, n = i & 127;
    float x = W[i];
    __half h = __float2half_rn(x);
    __half l = __float2half_rn(x - __half2float(h));
    Wh[(size_t)n * K + k] = h;
    Wl[(size_t)n * K + k] = l;
}

// ---------------- fp16-split tensor GEMM: C[M,128] = A[M,K]*W[K,128] --------
__device__ __forceinline__ void mma_f16(float* c, const uint32_t* a, const uint32_t* b) {
    asm volatile(
        "mma.sync.aligned.m16n8k16.row.col.f32.f16.f16.f32 "
        "{%0,%1,%2,%3}, {%4,%5,%6,%7}, {%8,%9}, {%0,%1,%2,%3};"
        : "+f"(c[0]), "+f"(c[1]), "+f"(c[2]), "+f"(c[3])
        : "r"(a[0]), "r"(a[1]), "r"(a[2]), "r"(a[3]), "r"(b[0]), "r"(b[1]));
}

#define ASTR 40   // halves per row (80B, 16B-aligned rows)
#define BSTR 40

__global__ __launch_bounds__(256) void gemm_fp16s_kernel(
    const float* __restrict__ A,
    const __half* __restrict__ Bh, const __half* __restrict__ Bl,
    float* __restrict__ C, __half* __restrict__ Ch, int M, int K)
{
    __shared__ __half Ash[64 * ASTR];
    __shared__ __half Asl[64 * ASTR];
    __shared__ __half Bsh[128 * BSTR];
    __shared__ __half Bsl[128 * BSTR];

    const int tid    = threadIdx.x;
    const int lane   = tid & 31;
    const int wid    = tid >> 5;
    const int warp_m = wid >> 2;    // 0..1
    const int warp_n = wid & 3;     // 0..3
    const int m0     = blockIdx.x * 64;
    const int g      = lane >> 2;   // 0..7
    const int t4     = lane & 3;    // 0..3

    float acc[2][4][4];
    #pragma unroll
    for (int i = 0; i < 2; i++)
        #pragma unroll
        for (int j = 0; j < 4; j++)
            #pragma unroll
            for (int k = 0; k < 4; k++) acc[i][j][k] = 0.f;

    for (int k0 = 0; k0 < K; k0 += 32) {
        // ---- A tile 64x32 fp32 -> split halves; 512 float4, 2 per thread ----
        #pragma unroll
        for (int i = 0; i < 2; i++) {
            int idx = tid + i * 256;
            int row = idx >> 3, c4 = idx & 7;
            float4 v = make_float4(0.f, 0.f, 0.f, 0.f);
            int grow = m0 + row;
            if (grow < M)
                v = *(const float4*)(A + (size_t)grow * K + k0 + c4 * 4);
            __half2 h01 = __floats2half2_rn(v.x, v.y);
            __half2 h23 = __floats2half2_rn(v.z, v.w);
            float2 f01 = __half22float2(h01);
            float2 f23 = __half22float2(h23);
            __half2 l01 = __floats2half2_rn(v.x - f01.x, v.y - f01.y);
            __half2 l23 = __floats2half2_rn(v.z - f23.x, v.w - f23.y);
            __half2* ph = (__half2*)&Ash[row * ASTR + c4 * 4];
            __half2* pl = (__half2*)&Asl[row * ASTR + c4 * 4];
            ph[0] = h01; ph[1] = h23;
            pl[0] = l01; pl[1] = l23;
        }
        // ---- B tile 128x32 halves (hi+lo); 512 int4 per split, 2/thread ----
        #pragma unroll
        for (int i = 0; i < 2; i++) {
            int idx = tid + i * 256;
            int row = idx >> 2, c8 = idx & 3;
            *(int4*)&Bsh[row * BSTR + c8 * 8] =
                *(const int4*)(Bh + (size_t)row * K + k0 + c8 * 8);
            *(int4*)&Bsl[row * BSTR + c8 * 8] =
                *(const int4*)(Bl + (size_t)row * K + k0 + c8 * 8);
        }
        __syncthreads();

        #pragma unroll
        for (int ks = 0; ks < 2; ks++) {
            const int kk = ks * 16;
            uint32_t ah[2][4], al[2][4];
            #pragma unroll
            for (int tm = 0; tm < 2; tm++) {
                int r = warp_m * 32 + tm * 16 + g;
                int c = kk + 2 * t4;
                ah[tm][0] = *(const uint32_t*)&Ash[r * ASTR + c];
                ah[tm][1] = *(const uint32_t*)&Ash[(r + 8) * ASTR + c];
                ah[tm][2] = *(const uint32_t*)&Ash[r * ASTR + c + 8];
                ah[tm][3] = *(const uint32_t*)&Ash[(r + 8) * ASTR + c + 8];
                al[tm][0] = *(const uint32_t*)&Asl[r * ASTR + c];
                al[tm][1] = *(const uint32_t*)&Asl[(r + 8) * ASTR + c];
                al[tm][2] = *(const uint32_t*)&Asl[r * ASTR + c + 8];
                al[tm][3] = *(const uint32_t*)&Asl[(r + 8) * ASTR + c + 8];
            }
            uint32_t bh[4][2], bl[4][2];
            #pragma unroll
            for (int tn = 0; tn < 4; tn++) {
                int n = warp_n * 32 + tn * 8 + g;
                int c = kk + 2 * t4;
                bh[tn][0] = *(const uint32_t*)&Bsh[n * BSTR + c];
                bh[tn][1] = *(const uint32_t*)&Bsh[n * BSTR + c + 8];
                bl[tn][0] = *(const uint32_t*)&Bsl[n * BSTR + c];
                bl[tn][1] = *(const uint32_t*)&Bsl[n * BSTR + c + 8];
            }
            #pragma unroll
            for (int tm = 0; tm < 2; tm++)
                #pragma unroll
                for (int tn = 0; tn < 4; tn++) {
                    mma_f16(acc[tm][tn], ah[tm], bh[tn]);
                    mma_f16(acc[tm][tn], ah[tm], bl[tn]);
                    mma_f16(acc[tm][tn], al[tm], bh[tn]);
                }
        }
        __syncthreads();
    }

    // store C (fp32) + Ch (fp16 mirror)
    #pragma unroll
    for (int tm = 0; tm < 2; tm++)
        #pragma unroll
        for (int tn = 0; tn < 4; tn++) {
            int row0 = m0 + warp_m * 32 + tm * 16 + g;
            int coln = warp_n * 32 + tn * 8 + t4 * 2;
            if (row0 < M) {
                *(float2*)(C + (size_t)row0 * 128 + coln) =
                    make_float2(acc[tm][tn][0], acc[tm][tn][1]);
                *(__half2*)(Ch + (size_t)row0 * 128 + coln) =
                    __floats2half2_rn(acc[tm][tn][0], acc[tm][tn][1]);
            }
            if (row0 + 8 < M) {
                *(float2*)(C + (size_t)(row0 + 8) * 128 + coln) =
                    make_float2(acc[tm][tn][2], acc[tm][tn][3]);
                *(__half2*)(Ch + (size_t)(row0 + 8) * 128 + coln) =
                    __floats2half2_rn(acc[tm][tn][2], acc[tm][tn][3]);
            }
        }
}

// ---------------- gather-aggregate: out = relu(sum + h*dinv^2 + b) ----------
// TWO warps per node: even warp does first half of edges + self-loop/bias,
// odd warp does second half, merges via smem. 256 thr = 8 warps = 4 nodes.
__global__ __launch_bounds__(256) void gather_kernel(
    const float* __restrict__ h, const __half* __restrict__ hh,
    const int2* __restrict__ edges,
    const int* __restrict__ off, const float* __restrict__ dinv,
    const float* __restrict__ bias, float* __restrict__ out, int N)
{
    __shared__ float sh[4][CH];

    const int wid  = threadIdx.x >> 5;   // 0..7
    const int lane = threadIdx.x & 31;
    const int slot = wid >> 1;           // 0..3 node slot in block
    const int half = wid & 1;            // 0 = first half + finalize
    const int node = blockIdx.x * 4 + slot;
    const bool valid = (node < N);

    float4 acc = make_float4(0.f, 0.f, 0.f, 0.f);
    int e = 0, e1 = 0;
    if (valid) {
        int a = __ldg(&off[node]);
        int b = __ldg(&off[node + 1]);
        int mid = a + ((b - a) >> 1);
        if (half == 0) {
            e = a; e1 = mid;
            float di = dinv[node];
            float dd = di * di;
            float4 hv = *(const float4*)(h + (size_t)node * CH + lane * 4);
            float4 bv = *(const float4*)(bias + lane * 4);
            acc.x = fmaf(hv.x, dd, bv.x);
            acc.y = fmaf(hv.y, dd, bv.y);
            acc.z = fmaf(hv.z, dd, bv.z);
            acc.w = fmaf(hv.w, dd, bv.w);
        } else {
            e = mid; e1 = b;
        }
    }

    for (; e + 3 < e1; e += 4) {
        int2 ev0 = __ldg(&edges[e]);
        int2 ev1 = __ldg(&edges[e + 1]);
        int2 ev2 = __ldg(&edges[e + 2]);
        int2 ev3 = __ldg(&edges[e + 3]);
        __half2 p0 = *(const __half2*)(hh + (size_t)ev0.x * CH + lane * 4);
        __half2 q0 = *(const __half2*)(hh + (size_t)ev0.x * CH + lane * 4 + 2);
        __half2 p1 = *(const __half2*)(hh + (size_t)ev1.x * CH + lane * 4);
        __half2 q1 = *(const __half2*)(hh + (size_t)ev1.x * CH + lane * 4 + 2);
        __half2 p2 = *(const __half2*)(hh + (size_t)ev2.x * CH + lane * 4);
        __half2 q2 = *(const __half2*)(hh + (size_t)ev2.x * CH + lane * 4 + 2);
        __half2 p3 = *(const __half2*)(hh + (size_t)ev3.x * CH + lane * 4);
        __half2 q3 = *(const __half2*)(hh + (size_t)ev3.x * CH + lane * 4 + 2);
        float w0 = __int_as_float(ev0.y);
        float w1 = __int_as_float(ev1.y);
        float w2 = __int_as_float(ev2.y);
        float w3 = __int_as_float(ev3.y);
        float2 a0 = __half22float2(p0), c0 = __half22float2(q0);
        float2 a1 = __half22float2(p1), c1 = __half22float2(q1);
        float2 a2 = __half22float2(p2), c2 = __half22float2(q2);
        float2 a3 = __half22float2(p3), c3 = __half22float2(q3);
        acc.x = fmaf(a0.x, w0, acc.x); acc.y = fmaf(a0.y, w0, acc.y);
        acc.z = fmaf(c0.x, w0, acc.z); acc.w = fmaf(c0.y, w0, acc.w);
        acc.x = fmaf(a1.x, w1, acc.x); acc.y = fmaf(a1.y, w1, acc.y);
        acc.z = fmaf(c1.x, w1, acc.z); acc.w = fmaf(c1.y, w1, acc.w);
        acc.x = fmaf(a2.x, w2, acc.x); acc.y = fmaf(a2.y, w2, acc.y);
        acc.z = fmaf(c2.x, w2, acc.z); acc.w = fmaf(c2.y, w2, acc.w);
        acc.x = fmaf(a3.x, w3, acc.x); acc.y = fmaf(a3.y, w3, acc.y);
        acc.z = fmaf(c3.x, w3, acc.z); acc.w = fmaf(c3.y, w3, acc.w);
    }
    for (; e < e1; e++) {
        int2 ev = __ldg(&edges[e]);
        __half2 p = *(const __half2*)(hh + (size_t)ev.x * CH + lane * 4);
        __half2 q = *(const __half2*)(hh + (size_t)ev.x * CH + lane * 4 + 2);
        float w = __int_as_float(ev.y);
        float2 a = __half22float2(p), c = __half22float2(q);
        acc.x = fmaf(a.x, w, acc.x); acc.y = fmaf(a.y, w, acc.y);
        acc.z = fmaf(c.x, w, acc.z); acc.w = fmaf(c.y, w, acc.w);
    }

    if (half == 1)
        *(float4*)&sh[slot][lane * 4] = acc;
    __syncthreads();
    if (half == 0 && valid) {
        float4 o = *(const float4*)&sh[slot][lane * 4];
        acc.x = fmaxf(acc.x + o.x, 0.f);
        acc.y = fmaxf(acc.y + o.y, 0.f);
        acc.z = fmaxf(acc.z + o.z, 0.f);
        acc.w = fmaxf(acc.w + o.w, 0.f);
        *(float4*)(out + (size_t)node * CH + lane * 4) = acc;
    }
}

// ---------------- launch ----------------------------------------------------
extern "C" void kernel_launch(void* const* d_in, const int* in_sizes, int n_in,
                              void* d_out, int out_size)
{
    const float* x   = (const float*)d_in[0];
    const int*   ei  = (const int*)  d_in[1];
    const float* W1  = (const float*)d_in[2];
    const float* b1  = (const float*)d_in[3];
    const float* W2  = (const float*)d_in[4];
    const float* b2  = (const float*)d_in[5];
    float*       out = (float*)d_out;

    const int K1 = 256;
    const int N  = in_sizes[0] / K1;   // 50000
    const int E  = in_sizes[1] / 2;    // 1.6M
    const int* src = ei;
    const int* dst = ei + E;

    int *cnt, *cur, *off, *part;  float *dinv, *h, *out1;  int2* edges;  __half* hh;
    __half *w1h, *w1l, *w2h, *w2l;
    cudaGetSymbolAddress((void**)&cnt,   g_cnt);
    cudaGetSymbolAddress((void**)&cur,   g_cur);
    cudaGetSymbolAddress((void**)&off,   g_off);
    cudaGetSymbolAddress((void**)&part,  g_part);
    cudaGetSymbolAddress((void**)&dinv,  g_dinv);
    cudaGetSymbolAddress((void**)&edges, g_edges);
    cudaGetSymbolAddress((void**)&h,     g_h);
    cudaGetSymbolAddress((void**)&hh,    g_hh);
    cudaGetSymbolAddress((void**)&out1,  g_out1);
    cudaGetSymbolAddress((void**)&w1h,   g_w1h);
    cudaGetSymbolAddress((void**)&w1l,   g_w1l);
    cudaGetSymbolAddress((void**)&w2h,   g_w2h);
    cudaGetSymbolAddress((void**)&w2l,   g_w2l);

    const int T  = 256;
    const int nb = (N + 1023) / 1024;

    // --- split weights + build CSR by dst (once; reused by both layers) ---
    wsplit_kernel    <<<(K1 * 128 + T - 1) / T, T>>>(W1, w1h, w1l, K1);
    wsplit_kernel    <<<(128 * 128 + T - 1) / T, T>>>(W2, w2h, w2l, 128);
    zero_cnt_kernel  <<<(N + T - 1) / T, T>>>(cnt, cur, N);
    count_kernel     <<<(E / 4 + T - 1) / T, T>>>(dst, cnt, E);
    dinv_kernel      <<<(N + T - 1) / T, T>>>(cnt, dinv, N);
    scan_part_kernel <<<nb, 256>>>(cnt, part, N);
    scan_tops_kernel <<<1, 128>>>(part, nb);
    scan_write_kernel<<<nb, 256>>>(cnt, part, off, N, E);
    fill_kernel      <<<(E + T - 1) / T, T>>>(src, dst, dinv, off, cur, edges, E);

    int gemm_blocks   = (N + 63) / 64;
    int gather_blocks = (N + 3) / 4;   // 4 nodes per block, 2 warps each

    // ---- layer 1 ----
    gemm_fp16s_kernel<<<gemm_blocks, 256>>>(x, w1h, w1l, h, hh, N, K1);
    gather_kernel    <<<gather_blocks, 256>>>(h, hh, edges, off, dinv, b1, out1, N);

    // ---- layer 2 ----
    gemm_fp16s_kernel<<<gemm_blocks, 256>>>(out1, w2h, w2l, h, hh, N, 128);
    gather_kernel    <<<gather_blocks, 256>>>(h, hh, edges, off, dinv, b2, out, N);
}

// round 15
// speedup vs baseline: 1.1015x; 1.1015x over previous
#include <cuda_runtime.h>
#include <cuda_fp16.h>
#include <cstdint>

#define MAX_N 50000
#define MAX_E 1600000
#define CH    128

// ---------------- scratch (static device globals) ---------------------------
__device__ int    g_cnt [MAX_N];
__device__ int    g_cur [MAX_N];
__device__ int    g_off [MAX_N + 1];
__device__ int    g_part[256];
__device__ float  g_dinv[MAX_N];
__device__ int2   g_edges[MAX_E];
__device__ float  g_h   [(size_t)MAX_N * CH];
__device__ __half g_hh  [(size_t)MAX_N * CH];   // fp16 mirror for edge gathers
__device__ float  g_out1[(size_t)MAX_N * CH];
// transposed + split weights: [N=128][K]
__device__ __half g_w1h[128 * 256];
__device__ __half g_w1l[128 * 256];
__device__ __half g_w2h[128 * 128];
__device__ __half g_w2l[128 * 128];

// ---------------- preprocessing ---------------------------------------------
__global__ void zero_cnt_kernel(int* cnt, int* cur, int n) {
    int i = blockIdx.x * blockDim.x + threadIdx.x;
    if (i < n) { cnt[i] = 0; cur[i] = 0; }
}

__global__ void count_kernel(const int* __restrict__ dst, int* cnt, int E) {
    int i = blockIdx.x * blockDim.x + threadIdx.x;
    if (i < E) atomicAdd(&cnt[dst[i]], 1);
}

// block partial sums for scan + dinv computation fused (both read cnt)
__global__ void scan_part_kernel(const int* __restrict__ cnt, int* __restrict__ part,
                                 float* __restrict__ dinv, int n) {
    __shared__ int sh[256];
    int b = blockIdx.x, t = threadIdx.x;
    int base = b * 1024 + t * 4;
    int s = 0;
    #pragma unroll
    for (int j = 0; j < 4; j++) {
        int i = base + j;
        if (i < n) {
            int c = cnt[i];
            s += c;
            dinv[i] = rsqrtf((float)c + 1.0f);   // +1 self loop
        }
    }
    sh[t] = s;
    __syncthreads();
    for (int o = 128; o > 0; o >>= 1) {
        if (t < o) sh[t] += sh[t + o];
        __syncthreads();
    }
    if (t == 0) part[b] = sh[0];
}

__global__ void scan_tops_kernel(int* part, int nb) {
    __shared__ int sh[128];
    int t = threadIdx.x;
    int v = (t < nb) ? part[t] : 0;
    sh[t] = v;
    __syncthreads();
    for (int o = 1; o < 128; o <<= 1) {
        int add = (t >= o) ? sh[t - o] : 0;
        __syncthreads();
        sh[t] += add;
        __syncthreads();
    }
    if (t < nb) part[t] = sh[t] - v;   // exclusive
}

__global__ void scan_write_kernel(const int* __restrict__ cnt, const int* __restrict__ part,
                                  int* __restrict__ off, int n, int E) {
    __shared__ int sh[256];
    int b = blockIdx.x, t = threadIdx.x;
    int base = b * 1024 + t * 4;
    int c[4]; int s = 0;
    #pragma unroll
    for (int j = 0; j < 4; j++) {
        c[j] = (base + j < n) ? cnt[base + j] : 0;
        s += c[j];
    }
    int v = s;
    sh[t] = s;
    __syncthreads();
    for (int o = 1; o < 256; o <<= 1) {
        int add = (t >= o) ? sh[t - o] : 0;
        __syncthreads();
        sh[t] += add;
        __syncthreads();
    }
    int ex = sh[t] - v + part[b];
    #pragma unroll
    for (int j = 0; j < 4; j++) {
        if (base + j < n) { off[base + j] = ex; ex += c[j]; }
    }
    if (b == 0 && t == 0) off[n] = E;
}

__global__ void fill_kernel(const int* __restrict__ src, const int* __restrict__ dst,
                            const float* __restrict__ dinv,
                            const int* __restrict__ off, int* __restrict__ cur,
                            int2* __restrict__ edges, int E)
{
    int e = blockIdx.x * blockDim.x + threadIdx.x;
    if (e >= E) return;
    int s = src[e], d = dst[e];
    float w = dinv[s] * dinv[d];
    int pos = off[d] + atomicAdd(&cur[d], 1);
    edges[pos] = make_int2(s, __float_as_int(w));
}

// transpose + fp16-split W[K][128] -> Wh/Wl[128][K]
__global__ void wsplit_kernel(const float* __restrict__ W,
                              __half* __restrict__ Wh, __half* __restrict__ Wl, int K)
{
    int i = blockIdx.x * blockDim.x + threadIdx.x;
    if (i >= K * 128) return;
    int k = i >> 7, n = i & 127;
    float x = W[i];
    __half h = __float2half_rn(x);
    __half l = __float2half_rn(x - __half2float(h));
    Wh[(size_t)n * K + k] = h;
    Wl[(size_t)n * K + k] = l;
}

// ---------------- fp16-split tensor GEMM: C[M,128] = A[M,K]*W[K,128] --------
__device__ __forceinline__ void mma_f16(float* c, const uint32_t* a, const uint32_t* b) {
    asm volatile(
        "mma.sync.aligned.m16n8k16.row.col.f32.f16.f16.f32 "
        "{%0,%1,%2,%3}, {%4,%5,%6,%7}, {%8,%9}, {%0,%1,%2,%3};"
        : "+f"(c[0]), "+f"(c[1]), "+f"(c[2]), "+f"(c[3])
        : "r"(a[0]), "r"(a[1]), "r"(a[2]), "r"(a[3]), "r"(b[0]), "r"(b[1]));
}

#define ASTR 40   // halves per row (80B, 16B-aligned rows)
#define BSTR 40

__global__ __launch_bounds__(256) void gemm_fp16s_kernel(
    const float* __restrict__ A,
    const __half* __restrict__ Bh, const __half* __restrict__ Bl,
    float* __restrict__ C, __half* __restrict__ Ch, int M, int K)
{
    __shared__ __half Ash[64 * ASTR];
    __shared__ __half Asl[64 * ASTR];
    __shared__ __half Bsh[128 * BSTR];
    __shared__ __half Bsl[128 * BSTR];

    const int tid    = threadIdx.x;
    const int lane   = tid & 31;
    const int wid    = tid >> 5;
    const int warp_m = wid >> 2;    // 0..1
    const int warp_n = wid & 3;     // 0..3
    const int m0     = blockIdx.x * 64;
    const int g      = lane >> 2;   // 0..7
    const int t4     = lane & 3;    // 0..3

    float acc[2][4][4];
    #pragma unroll
    for (int i = 0; i < 2; i++)
        #pragma unroll
        for (int j = 0; j < 4; j++)
            #pragma unroll
            for (int k = 0; k < 4; k++) acc[i][j][k] = 0.f;

    for (int k0 = 0; k0 < K; k0 += 32) {
        // ---- A tile 64x32 fp32 -> split halves; 512 float4, 2 per thread ----
        #pragma unroll
        for (int i = 0; i < 2; i++) {
            int idx = tid + i * 256;
            int row = idx >> 3, c4 = idx & 7;
            float4 v = make_float4(0.f, 0.f, 0.f, 0.f);
            int grow = m0 + row;
            if (grow < M)
                v = *(const float4*)(A + (size_t)grow * K + k0 + c4 * 4);
            __half2 h01 = __floats2half2_rn(v.x, v.y);
            __half2 h23 = __floats2half2_rn(v.z, v.w);
            float2 f01 = __half22float2(h01);
            float2 f23 = __half22float2(h23);
            __half2 l01 = __floats2half2_rn(v.x - f01.x, v.y - f01.y);
            __half2 l23 = __floats2half2_rn(v.z - f23.x, v.w - f23.y);
            __half2* ph = (__half2*)&Ash[row * ASTR + c4 * 4];
            __half2* pl = (__half2*)&Asl[row * ASTR + c4 * 4];
            ph[0] = h01; ph[1] = h23;
            pl[0] = l01; pl[1] = l23;
        }
        // ---- B tile 128x32 halves (hi+lo); 512 int4 per split, 2/thread ----
        #pragma unroll
        for (int i = 0; i < 2; i++) {
            int idx = tid + i * 256;
            int row = idx >> 2, c8 = idx & 3;
            *(int4*)&Bsh[row * BSTR + c8 * 8] =
                *(const int4*)(Bh + (size_t)row * K + k0 + c8 * 8);
            *(int4*)&Bsl[row * BSTR + c8 * 8] =
                *(const int4*)(Bl + (size_t)row * K + k0 + c8 * 8);
        }
        __syncthreads();

        #pragma unroll
        for (int ks = 0; ks < 2; ks++) {
            const int kk = ks * 16;
            uint32_t ah[2][4], al[2][4];
            #pragma unroll
            for (int tm = 0; tm < 2; tm++) {
                int r = warp_m * 32 + tm * 16 + g;
                int c = kk + 2 * t4;
                ah[tm][0] = *(const uint32_t*)&Ash[r * ASTR + c];
                ah[tm][1] = *(const uint32_t*)&Ash[(r + 8) * ASTR + c];
                ah[tm][2] = *(const uint32_t*)&Ash[r * ASTR + c + 8];
                ah[tm][3] = *(const uint32_t*)&Ash[(r + 8) * ASTR + c + 8];
                al[tm][0] = *(const uint32_t*)&Asl[r * ASTR + c];
                al[tm][1] = *(const uint32_t*)&Asl[(r + 8) * ASTR + c];
                al[tm][2] = *(const uint32_t*)&Asl[r * ASTR + c + 8];
                al[tm][3] = *(const uint32_t*)&Asl[(r + 8) * ASTR + c + 8];
            }
            uint32_t bh[4][2], bl[4][2];
            #pragma unroll
            for (int tn = 0; tn < 4; tn++) {
                int n = warp_n * 32 + tn * 8 + g;
                int c = kk + 2 * t4;
                bh[tn][0] = *(const uint32_t*)&Bsh[n * BSTR + c];
                bh[tn][1] = *(const uint32_t*)&Bsh[n * BSTR + c + 8];
                bl[tn][0] = *(const uint32_t*)&Bsl[n * BSTR + c];
                bl[tn][1] = *(const uint32_t*)&Bsl[n * BSTR + c + 8];
            }
            #pragma unroll
            for (int tm = 0; tm < 2; tm++)
                #pragma unroll
                for (int tn = 0; tn < 4; tn++) {
                    mma_f16(acc[tm][tn], ah[tm], bh[tn]);
                    mma_f16(acc[tm][tn], ah[tm], bl[tn]);
                    mma_f16(acc[tm][tn], al[tm], bh[tn]);
                }
        }
        __syncthreads();
    }

    // store C (fp32) + Ch (fp16 mirror)
    #pragma unroll
    for (int tm = 0; tm < 2; tm++)
        #pragma unroll
        for (int tn = 0; tn < 4; tn++) {
            int row0 = m0 + warp_m * 32 + tm * 16 + g;
            int coln = warp_n * 32 + tn * 8 + t4 * 2;
            if (row0 < M) {
                *(float2*)(C + (size_t)row0 * 128 + coln) =
                    make_float2(acc[tm][tn][0], acc[tm][tn][1]);
                *(__half2*)(Ch + (size_t)row0 * 128 + coln) =
                    __floats2half2_rn(acc[tm][tn][0], acc[tm][tn][1]);
            }
            if (row0 + 8 < M) {
                *(float2*)(C + (size_t)(row0 + 8) * 128 + coln) =
                    make_float2(acc[tm][tn][2], acc[tm][tn][3]);
                *(__half2*)(Ch + (size_t)(row0 + 8) * 128 + coln) =
                    __floats2half2_rn(acc[tm][tn][2], acc[tm][tn][3]);
            }
        }
}

// ---------------- gather-aggregate: out = relu(sum + h*dinv^2 + b) ----------
// one warp per dst node; lane owns 4 channels; neighbors read fp16 mirror.
__global__ __launch_bounds__(256) void gather_kernel(
    const float* __restrict__ h, const __half* __restrict__ hh,
    const int2* __restrict__ edges,
    const int* __restrict__ off, const float* __restrict__ dinv,
    const float* __restrict__ bias, float* __restrict__ out, int N)
{
    int node = (blockIdx.x * blockDim.x + threadIdx.x) >> 5;
    int lane = threadIdx.x & 31;
    if (node >= N) return;

    float di = dinv[node];
    float dd = di * di;
    float4 hv = *(const float4*)(h + (size_t)node * CH + lane * 4);
    float4 bv = *(const float4*)(bias + lane * 4);
    float4 acc;
    acc.x = fmaf(hv.x, dd, bv.x);
    acc.y = fmaf(hv.y, dd, bv.y);
    acc.z = fmaf(hv.z, dd, bv.z);
    acc.w = fmaf(hv.w, dd, bv.w);

    int e  = __ldg(&off[node]);
    int e1 = __ldg(&off[node + 1]);

    for (; e + 3 < e1; e += 4) {
        int2 ev0 = __ldg(&edges[e]);
        int2 ev1 = __ldg(&edges[e + 1]);
        int2 ev2 = __ldg(&edges[e + 2]);
        int2 ev3 = __ldg(&edges[e + 3]);
        __half2 p0 = *(const __half2*)(hh + (size_t)ev0.x * CH + lane * 4);
        __half2 q0 = *(const __half2*)(hh + (size_t)ev0.x * CH + lane * 4 + 2);
        __half2 p1 = *(const __half2*)(hh + (size_t)ev1.x * CH + lane * 4);
        __half2 q1 = *(const __half2*)(hh + (size_t)ev1.x * CH + lane * 4 + 2);
        __half2 p2 = *(const __half2*)(hh + (size_t)ev2.x * CH + lane * 4);
        __half2 q2 = *(const __half2*)(hh + (size_t)ev2.x * CH + lane * 4 + 2);
        __half2 p3 = *(const __half2*)(hh + (size_t)ev3.x * CH + lane * 4);
        __half2 q3 = *(const __half2*)(hh + (size_t)ev3.x * CH + lane * 4 + 2);
        float w0 = __int_as_float(ev0.y);
        float w1 = __int_as_float(ev1.y);
        float w2 = __int_as_float(ev2.y);
        float w3 = __int_as_float(ev3.y);
        float2 a0 = __half22float2(p0), c0 = __half22float2(q0);
        float2 a1 = __half22float2(p1), c1 = __half22float2(q1);
        float2 a2 = __half22float2(p2), c2 = __half22float2(q2);
        float2 a3 = __half22float2(p3), c3 = __half22float2(q3);
        acc.x = fmaf(a0.x, w0, acc.x); acc.y = fmaf(a0.y, w0, acc.y);
        acc.z = fmaf(c0.x, w0, acc.z); acc.w = fmaf(c0.y, w0, acc.w);
        acc.x = fmaf(a1.x, w1, acc.x); acc.y = fmaf(a1.y, w1, acc.y);
        acc.z = fmaf(c1.x, w1, acc.z); acc.w = fmaf(c1.y, w1, acc.w);
        acc.x = fmaf(a2.x, w2, acc.x); acc.y = fmaf(a2.y, w2, acc.y);
        acc.z = fmaf(c2.x, w2, acc.z); acc.w = fmaf(c2.y, w2, acc.w);
        acc.x = fmaf(a3.x, w3, acc.x); acc.y = fmaf(a3.y, w3, acc.y);
        acc.z = fmaf(c3.x, w3, acc.z); acc.w = fmaf(c3.y, w3, acc.w);
    }
    for (; e < e1; e++) {
        int2 ev = __ldg(&edges[e]);
        __half2 p = *(const __half2*)(hh + (size_t)ev.x * CH + lane * 4);
        __half2 q = *(const __half2*)(hh + (size_t)ev.x * CH + lane * 4 + 2);
        float w = __int_as_float(ev.y);
        float2 a = __half22float2(p), c = __half22float2(q);
        acc.x = fmaf(a.x, w, acc.x); acc.y = fmaf(a.y, w, acc.y);
        acc.z = fmaf(c.x, w, acc.z); acc.w = fmaf(c.y, w, acc.w);
    }

    acc.x = fmaxf(acc.x, 0.f);
    acc.y = fmaxf(acc.y, 0.f);
    acc.z = fmaxf(acc.z, 0.f);
    acc.w = fmaxf(acc.w, 0.f);
    *(float4*)(out + (size_t)node * CH + lane * 4) = acc;
}

// ---------------- launch ----------------------------------------------------
extern "C" void kernel_launch(void* const* d_in, const int* in_sizes, int n_in,
                              void* d_out, int out_size)
{
    const float* x   = (const float*)d_in[0];
    const int*   ei  = (const int*)  d_in[1];
    const float* W1  = (const float*)d_in[2];
    const float* b1  = (const float*)d_in[3];
    const float* W2  = (const float*)d_in[4];
    const float* b2  = (const float*)d_in[5];
    float*       out = (float*)d_out;

    const int K1 = 256;
    const int N  = in_sizes[0] / K1;   // 50000
    const int E  = in_sizes[1] / 2;    // 1.6M
    const int* src = ei;
    const int* dst = ei + E;

    int *cnt, *cur, *off, *part;  float *dinv, *h, *out1;  int2* edges;  __half* hh;
    __half *w1h, *w1l, *w2h, *w2l;
    cudaGetSymbolAddress((void**)&cnt,   g_cnt);
    cudaGetSymbolAddress((void**)&cur,   g_cur);
    cudaGetSymbolAddress((void**)&off,   g_off);
    cudaGetSymbolAddress((void**)&part,  g_part);
    cudaGetSymbolAddress((void**)&dinv,  g_dinv);
    cudaGetSymbolAddress((void**)&edges, g_edges);
    cudaGetSymbolAddress((void**)&h,     g_h);
    cudaGetSymbolAddress((void**)&hh,    g_hh);
    cudaGetSymbolAddress((void**)&out1,  g_out1);
    cudaGetSymbolAddress((void**)&w1h,   g_w1h);
    cudaGetSymbolAddress((void**)&w1l,   g_w1l);
    cudaGetSymbolAddress((void**)&w2h,   g_w2h);
    cudaGetSymbolAddress((void**)&w2l,   g_w2l);

    // side stream + events for capture-safe fork/join (created once; host objects)
    static cudaStream_t s_side = nullptr;
    static cudaEvent_t  ev_fork = nullptr, ev_csr = nullptr;
    if (s_side == nullptr) {
        cudaStreamCreateWithFlags(&s_side, cudaStreamNonBlocking);
        cudaEventCreateWithFlags(&ev_fork, cudaEventDisableTiming);
        cudaEventCreateWithFlags(&ev_csr,  cudaEventDisableTiming);
    }

    const int T  = 256;
    const int nb = (N + 1023) / 1024;

    // --- fork: CSR build on side stream, concurrent with wsplit + GEMM1 ---
    cudaEventRecord(ev_fork, 0);
    cudaStreamWaitEvent(s_side, ev_fork, 0);

    zero_cnt_kernel  <<<(N + T - 1) / T, T, 0, s_side>>>(cnt, cur, N);
    count_kernel     <<<(E + T - 1) / T, T, 0, s_side>>>(dst, cnt, E);
    scan_part_kernel <<<nb, 256, 0, s_side>>>(cnt, part, dinv, N);
    scan_tops_kernel <<<1, 128, 0, s_side>>>(part, nb);
    scan_write_kernel<<<nb, 256, 0, s_side>>>(cnt, part, off, N, E);
    fill_kernel      <<<(E + T - 1) / T, T, 0, s_side>>>(src, dst, dinv, off, cur, edges, E);
    cudaEventRecord(ev_csr, s_side);

    int gemm_blocks   = (N + 63) / 64;
    int gather_blocks = (N + 7) / 8;

    // main stream: weights + layer-1 GEMM (independent of CSR build)
    wsplit_kernel    <<<(K1 * 128 + T - 1) / T, T>>>(W1, w1h, w1l, K1);
    wsplit_kernel    <<<(128 * 128 + T - 1) / T, T>>>(W2, w2h, w2l, 128);
    gemm_fp16s_kernel<<<gemm_blocks, 256>>>(x, w1h, w1l, h, hh, N, K1);

    // join: gather-1 needs both GEMM1 output and CSR
    cudaStreamWaitEvent(0, ev_csr, 0);
    gather_kernel    <<<gather_blocks, 256>>>(h, hh, edges, off, dinv, b1, out1, N);

    // ---- layer 2 ----
    gemm_fp16s_kernel<<<gemm_blocks, 256>>>(out1, w2h, w2l, h, hh, N, 128);
    gather_kernel    <<<gather_blocks, 256>>>(h, hh, edges, off, dinv, b2, out, N);
}

// round 16
// speedup vs baseline: 1.2019x; 1.0911x over previous
#include <cuda_runtime.h>
#include <cuda_fp16.h>
#include <cstdint>

#define MAX_N 50000
#define MAX_E 1600000
#define CH    128

// ---------------- scratch (static device globals) ---------------------------
__device__ int    g_cnt [MAX_N];
__device__ int    g_cur [MAX_N];
__device__ int    g_off [MAX_N + 1];
__device__ int    g_part[256];
__device__ float  g_dinv[MAX_N];
__device__ int2   g_edges[MAX_E];
__device__ __half g_hh  [(size_t)MAX_N * CH];   // fp16 activations (GEMM out)
__device__ float  g_out1[(size_t)MAX_N * CH];
// transposed + split weights: [N=128][K]
__device__ __half g_w1h[128 * 256];
__device__ __half g_w1l[128 * 256];
__device__ __half g_w2h[128 * 128];
__device__ __half g_w2l[128 * 128];

// ---------------- preprocessing ---------------------------------------------
__global__ void zero_cnt_kernel(int* cnt, int* cur, int n) {
    int i = blockIdx.x * blockDim.x + threadIdx.x;
    if (i < n) { cnt[i] = 0; cur[i] = 0; }
}

__global__ void count_kernel(const int* __restrict__ dst, int* cnt, int E) {
    int i = blockIdx.x * blockDim.x + threadIdx.x;
    if (i < E) atomicAdd(&cnt[dst[i]], 1);
}

// block partial sums for scan + dinv computation fused (both read cnt)
__global__ void scan_part_kernel(const int* __restrict__ cnt, int* __restrict__ part,
                                 float* __restrict__ dinv, int n) {
    __shared__ int sh[256];
    int b = blockIdx.x, t = threadIdx.x;
    int base = b * 1024 + t * 4;
    int s = 0;
    #pragma unroll
    for (int j = 0; j < 4; j++) {
        int i = base + j;
        if (i < n) {
            int c = cnt[i];
            s += c;
            dinv[i] = rsqrtf((float)c + 1.0f);   // +1 self loop
        }
    }
    sh[t] = s;
    __syncthreads();
    for (int o = 128; o > 0; o >>= 1) {
        if (t < o) sh[t] += sh[t + o];
        __syncthreads();
    }
    if (t == 0) part[b] = sh[0];
}

__global__ void scan_tops_kernel(int* part, int nb) {
    __shared__ int sh[128];
    int t = threadIdx.x;
    int v = (t < nb) ? part[t] : 0;
    sh[t] = v;
    __syncthreads();
    for (int o = 1; o < 128; o <<= 1) {
        int add = (t >= o) ? sh[t - o] : 0;
        __syncthreads();
        sh[t] += add;
        __syncthreads();
    }
    if (t < nb) part[t] = sh[t] - v;   // exclusive
}

__global__ void scan_write_kernel(const int* __restrict__ cnt, const int* __restrict__ part,
                                  int* __restrict__ off, int n, int E) {
    __shared__ int sh[256];
    int b = blockIdx.x, t = threadIdx.x;
    int base = b * 1024 + t * 4;
    int c[4]; int s = 0;
    #pragma unroll
    for (int j = 0; j < 4; j++) {
        c[j] = (base + j < n) ? cnt[base + j] : 0;
        s += c[j];
    }
    int v = s;
    sh[t] = s;
    __syncthreads();
    for (int o = 1; o < 256; o <<= 1) {
        int add = (t >= o) ? sh[t - o] : 0;
        __syncthreads();
        sh[t] += add;
        __syncthreads();
    }
    int ex = sh[t] - v + part[b];
    #pragma unroll
    for (int j = 0; j < 4; j++) {
        if (base + j < n) { off[base + j] = ex; ex += c[j]; }
    }
    if (b == 0 && t == 0) off[n] = E;
}

__global__ void fill_kernel(const int* __restrict__ src, const int* __restrict__ dst,
                            const float* __restrict__ dinv,
                            const int* __restrict__ off, int* __restrict__ cur,
                            int2* __restrict__ edges, int E)
{
    int e = blockIdx.x * blockDim.x + threadIdx.x;
    if (e >= E) return;
    int s = src[e], d = dst[e];
    float w = dinv[s] * dinv[d];
    int pos = off[d] + atomicAdd(&cur[d], 1);
    edges[pos] = make_int2(s, __float_as_int(w));
}

// transpose + fp16-split W[K][128] -> Wh/Wl[128][K]
__global__ void wsplit_kernel(const float* __restrict__ W,
                              __half* __restrict__ Wh, __half* __restrict__ Wl, int K)
{
    int i = blockIdx.x * blockDim.x + threadIdx.x;
    if (i >= K * 128) return;
    int k = i >> 7, n = i & 127;
    float x = W[i];
    __half h = __float2half_rn(x);
    __half l = __float2half_rn(x - __half2float(h));
    Wh[(size_t)n * K + k] = h;
    Wl[(size_t)n * K + k] = l;
}

// ---------------- fp16-split tensor GEMM: Ch[M,128] = A[M,K]*W[K,128] -------
__device__ __forceinline__ void mma_f16(float* c, const uint32_t* a, const uint32_t* b) {
    asm volatile(
        "mma.sync.aligned.m16n8k16.row.col.f32.f16.f16.f32 "
        "{%0,%1,%2,%3}, {%4,%5,%6,%7}, {%8,%9}, {%0,%1,%2,%3};"
        : "+f"(c[0]), "+f"(c[1]), "+f"(c[2]), "+f"(c[3])
        : "r"(a[0]), "r"(a[1]), "r"(a[2]), "r"(a[3]), "r"(b[0]), "r"(b[1]));
}

#define ASTR 40   // halves per row (80B, 16B-aligned rows)
#define BSTR 40

__global__ __launch_bounds__(256) void gemm_fp16s_kernel(
    const float* __restrict__ A,
    const __half* __restrict__ Bh, const __half* __restrict__ Bl,
    __half* __restrict__ Ch, int M, int K)
{
    __shared__ __half Ash[64 * ASTR];
    __shared__ __half Asl[64 * ASTR];
    __shared__ __half Bsh[128 * BSTR];
    __shared__ __half Bsl[128 * BSTR];

    const int tid    = threadIdx.x;
    const int lane   = tid & 31;
    const int wid    = tid >> 5;
    const int warp_m = wid >> 2;    // 0..1
    const int warp_n = wid & 3;     // 0..3
    const int m0     = blockIdx.x * 64;
    const int g      = lane >> 2;   // 0..7
    const int t4     = lane & 3;    // 0..3

    float acc[2][4][4];
    #pragma unroll
    for (int i = 0; i < 2; i++)
        #pragma unroll
        for (int j = 0; j < 4; j++)
            #pragma unroll
            for (int k = 0; k < 4; k++) acc[i][j][k] = 0.f;

    for (int k0 = 0; k0 < K; k0 += 32) {
        // ---- A tile 64x32 fp32 -> split halves; 512 float4, 2 per thread ----
        #pragma unroll
        for (int i = 0; i < 2; i++) {
            int idx = tid + i * 256;
            int row = idx >> 3, c4 = idx & 7;
            float4 v = make_float4(0.f, 0.f, 0.f, 0.f);
            int grow = m0 + row;
            if (grow < M)
                v = *(const float4*)(A + (size_t)grow * K + k0 + c4 * 4);
            __half2 h01 = __floats2half2_rn(v.x, v.y);
            __half2 h23 = __floats2half2_rn(v.z, v.w);
            float2 f01 = __half22float2(h01);
            float2 f23 = __half22float2(h23);
            __half2 l01 = __floats2half2_rn(v.x - f01.x, v.y - f01.y);
            __half2 l23 = __floats2half2_rn(v.z - f23.x, v.w - f23.y);
            __half2* ph = (__half2*)&Ash[row * ASTR + c4 * 4];
            __half2* pl = (__half2*)&Asl[row * ASTR + c4 * 4];
            ph[0] = h01; ph[1] = h23;
            pl[0] = l01; pl[1] = l23;
        }
        // ---- B tile 128x32 halves (hi+lo); 512 int4 per split, 2/thread ----
        #pragma unroll
        for (int i = 0; i < 2; i++) {
            int idx = tid + i * 256;
            int row = idx >> 2, c8 = idx & 3;
            *(int4*)&Bsh[row * BSTR + c8 * 8] =
                *(const int4*)(Bh + (size_t)row * K + k0 + c8 * 8);
            *(int4*)&Bsl[row * BSTR + c8 * 8] =
                *(const int4*)(Bl + (size_t)row * K + k0 + c8 * 8);
        }
        __syncthreads();

        #pragma unroll
        for (int ks = 0; ks < 2; ks++) {
            const int kk = ks * 16;
            uint32_t ah[2][4], al[2][4];
            #pragma unroll
            for (int tm = 0; tm < 2; tm++) {
                int r = warp_m * 32 + tm * 16 + g;
                int c = kk + 2 * t4;
                ah[tm][0] = *(const uint32_t*)&Ash[r * ASTR + c];
                ah[tm][1] = *(const uint32_t*)&Ash[(r + 8) * ASTR + c];
                ah[tm][2] = *(const uint32_t*)&Ash[r * ASTR + c + 8];
                ah[tm][3] = *(const uint32_t*)&Ash[(r + 8) * ASTR + c + 8];
                al[tm][0] = *(const uint32_t*)&Asl[r * ASTR + c];
                al[tm][1] = *(const uint32_t*)&Asl[(r + 8) * ASTR + c];
                al[tm][2] = *(const uint32_t*)&Asl[r * ASTR + c + 8];
                al[tm][3] = *(const uint32_t*)&Asl[(r + 8) * ASTR + c + 8];
            }
            uint32_t bh[4][2], bl[4][2];
            #pragma unroll
            for (int tn = 0; tn < 4; tn++) {
                int n = warp_n * 32 + tn * 8 + g;
                int c = kk + 2 * t4;
                bh[tn][0] = *(const uint32_t*)&Bsh[n * BSTR + c];
                bh[tn][1] = *(const uint32_t*)&Bsh[n * BSTR + c + 8];
                bl[tn][0] = *(const uint32_t*)&Bsl[n * BSTR + c];
                bl[tn][1] = *(const uint32_t*)&Bsl[n * BSTR + c + 8];
            }
            #pragma unroll
            for (int tm = 0; tm < 2; tm++)
                #pragma unroll
                for (int tn = 0; tn < 4; tn++) {
                    mma_f16(acc[tm][tn], ah[tm], bh[tn]);
                    mma_f16(acc[tm][tn], ah[tm], bl[tn]);
                    mma_f16(acc[tm][tn], al[tm], bh[tn]);
                }
        }
        __syncthreads();
    }

    // store Ch (fp16) only — fp32 copy no longer needed downstream
    #pragma unroll
    for (int tm = 0; tm < 2; tm++)
        #pragma unroll
        for (int tn = 0; tn < 4; tn++) {
            int row0 = m0 + warp_m * 32 + tm * 16 + g;
            int coln = warp_n * 32 + tn * 8 + t4 * 2;
            if (row0 < M) {
                *(__half2*)(Ch + (size_t)row0 * 128 + coln) =
                    __floats2half2_rn(acc[tm][tn][0], acc[tm][tn][1]);
            }
            if (row0 + 8 < M) {
                *(__half2*)(Ch + (size_t)(row0 + 8) * 128 + coln) =
                    __floats2half2_rn(acc[tm][tn][2], acc[tm][tn][3]);
            }
        }
}

// ---------------- gather-aggregate: out = relu(sum + h*dinv^2 + b) ----------
// one warp per dst node; lane owns 4 channels; single 8B load per edge-lane.
__global__ __launch_bounds__(256) void gather_kernel(
    const __half* __restrict__ hh, const int2* __restrict__ edges,
    const int* __restrict__ off, const float* __restrict__ dinv,
    const float* __restrict__ bias, float* __restrict__ out, int N)
{
    int node = (blockIdx.x * blockDim.x + threadIdx.x) >> 5;
    int lane = threadIdx.x & 31;
    if (node >= N) return;

    float di = dinv[node];
    float dd = di * di;
    uint2 rs = *(const uint2*)(hh + (size_t)node * CH + lane * 4);
    float2 s0 = __half22float2(*(const __half2*)&rs.x);
    float2 s1 = __half22float2(*(const __half2*)&rs.y);
    float4 bv = *(const float4*)(bias + lane * 4);
    float4 acc;
    acc.x = fmaf(s0.x, dd, bv.x);
    acc.y = fmaf(s0.y, dd, bv.y);
    acc.z = fmaf(s1.x, dd, bv.z);
    acc.w = fmaf(s1.y, dd, bv.w);

    int e  = __ldg(&off[node]);
    int e1 = __ldg(&off[node + 1]);

    for (; e + 3 < e1; e += 4) {
        int2 ev0 = __ldg(&edges[e]);
        int2 ev1 = __ldg(&edges[e + 1]);
        int2 ev2 = __ldg(&edges[e + 2]);
        int2 ev3 = __ldg(&edges[e + 3]);
        uint2 r0 = *(const uint2*)(hh + (size_t)ev0.x * CH + lane * 4);
        uint2 r1 = *(const uint2*)(hh + (size_t)ev1.x * CH + lane * 4);
        uint2 r2 = *(const uint2*)(hh + (size_t)ev2.x * CH + lane * 4);
        uint2 r3 = *(const uint2*)(hh + (size_t)ev3.x * CH + lane * 4);
        float w0 = __int_as_float(ev0.y);
        float w1 = __int_as_float(ev1.y);
        float w2 = __int_as_float(ev2.y);
        float w3 = __int_as_float(ev3.y);
        float2 a0 = __half22float2(*(const __half2*)&r0.x);
        float2 c0 = __half22float2(*(const __half2*)&r0.y);
        float2 a1 = __half22float2(*(const __half2*)&r1.x);
        float2 c1 = __half22float2(*(const __half2*)&r1.y);
        float2 a2 = __half22float2(*(const __half2*)&r2.x);
        float2 c2 = __half22float2(*(const __half2*)&r2.y);
        float2 a3 = __half22float2(*(const __half2*)&r3.x);
        float2 c3 = __half22float2(*(const __half2*)&r3.y);
        acc.x = fmaf(a0.x, w0, acc.x); acc.y = fmaf(a0.y, w0, acc.y);
        acc.z = fmaf(c0.x, w0, acc.z); acc.w = fmaf(c0.y, w0, acc.w);
        acc.x = fmaf(a1.x, w1, acc.x); acc.y = fmaf(a1.y, w1, acc.y);
        acc.z = fmaf(c1.x, w1, acc.z); acc.w = fmaf(c1.y, w1, acc.w);
        acc.x = fmaf(a2.x, w2, acc.x); acc.y = fmaf(a2.y, w2, acc.y);
        acc.z = fmaf(c2.x, w2, acc.z); acc.w = fmaf(c2.y, w2, acc.w);
        acc.x = fmaf(a3.x, w3, acc.x); acc.y = fmaf(a3.y, w3, acc.y);
        acc.z = fmaf(c3.x, w3, acc.z); acc.w = fmaf(c3.y, w3, acc.w);
    }
    for (; e < e1; e++) {
        int2 ev = __ldg(&edges[e]);
        uint2 r = *(const uint2*)(hh + (size_t)ev.x * CH + lane * 4);
        float w = __int_as_float(ev.y);
        float2 a = __half22float2(*(const __half2*)&r.x);
        float2 c = __half22float2(*(const __half2*)&r.y);
        acc.x = fmaf(a.x, w, acc.x); acc.y = fmaf(a.y, w, acc.y);
        acc.z = fmaf(c.x, w, acc.z); acc.w = fmaf(c.y, w, acc.w);
    }

    acc.x = fmaxf(acc.x, 0.f);
    acc.y = fmaxf(acc.y, 0.f);
    acc.z = fmaxf(acc.z, 0.f);
    acc.w = fmaxf(acc.w, 0.f);
    *(float4*)(out + (size_t)node * CH + lane * 4) = acc;
}

// ---------------- launch ----------------------------------------------------
extern "C" void kernel_launch(void* const* d_in, const int* in_sizes, int n_in,
                              void* d_out, int out_size)
{
    const float* x   = (const float*)d_in[0];
    const int*   ei  = (const int*)  d_in[1];
    const float* W1  = (const float*)d_in[2];
    const float* b1  = (const float*)d_in[3];
    const float* W2  = (const float*)d_in[4];
    const float* b2  = (const float*)d_in[5];
    float*       out = (float*)d_out;

    const int K1 = 256;
    const int N  = in_sizes[0] / K1;   // 50000
    const int E  = in_sizes[1] / 2;    // 1.6M
    const int* src = ei;
    const int* dst = ei + E;

    int *cnt, *cur, *off, *part;  float *dinv, *out1;  int2* edges;  __half* hh;
    __half *w1h, *w1l, *w2h, *w2l;
    cudaGetSymbolAddress((void**)&cnt,   g_cnt);
    cudaGetSymbolAddress((void**)&cur,   g_cur);
    cudaGetSymbolAddress((void**)&off,   g_off);
    cudaGetSymbolAddress((void**)&part,  g_part);
    cudaGetSymbolAddress((void**)&dinv,  g_dinv);
    cudaGetSymbolAddress((void**)&edges, g_edges);
    cudaGetSymbolAddress((void**)&hh,    g_hh);
    cudaGetSymbolAddress((void**)&out1,  g_out1);
    cudaGetSymbolAddress((void**)&w1h,   g_w1h);
    cudaGetSymbolAddress((void**)&w1l,   g_w1l);
    cudaGetSymbolAddress((void**)&w2h,   g_w2h);
    cudaGetSymbolAddress((void**)&w2l,   g_w2l);

    // side stream + events for capture-safe fork/join (created once; host objects)
    static cudaStream_t s_side = nullptr;
    static cudaEvent_t  ev_fork = nullptr, ev_csr = nullptr;
    if (s_side == nullptr) {
        cudaStreamCreateWithFlags(&s_side, cudaStreamNonBlocking);
        cudaEventCreateWithFlags(&ev_fork, cudaEventDisableTiming);
        cudaEventCreateWithFlags(&ev_csr,  cudaEventDisableTiming);
    }

    const int T  = 256;
    const int nb = (N + 1023) / 1024;

    // --- fork: CSR build on side stream, concurrent with wsplit + GEMM1 ---
    cudaEventRecord(ev_fork, 0);
    cudaStreamWaitEvent(s_side, ev_fork, 0);

    zero_cnt_kernel  <<<(N + T - 1) / T, T, 0, s_side>>>(cnt, cur, N);
    count_kernel     <<<(E + T - 1) / T, T, 0, s_side>>>(dst, cnt, E);
    scan_part_kernel <<<nb, 256, 0, s_side>>>(cnt, part, dinv, N);
    scan_tops_kernel <<<1, 128, 0, s_side>>>(part, nb);
    scan_write_kernel<<<nb, 256, 0, s_side>>>(cnt, part, off, N, E);
    fill_kernel      <<<(E + T - 1) / T, T, 0, s_side>>>(src, dst, dinv, off, cur, edges, E);
    cudaEventRecord(ev_csr, s_side);

    int gemm_blocks   = (N + 63) / 64;
    int gather_blocks = (N + 7) / 8;

    // main stream: weights + layer-1 GEMM (independent of CSR build)
    wsplit_kernel    <<<(K1 * 128 + T - 1) / T, T>>>(W1, w1h, w1l, K1);
    wsplit_kernel    <<<(128 * 128 + T - 1) / T, T>>>(W2, w2h, w2l, 128);
    gemm_fp16s_kernel<<<gemm_blocks, 256>>>(x, w1h, w1l, hh, N, K1);

    // join: gather-1 needs both GEMM1 output and CSR
    cudaStreamWaitEvent(0, ev_csr, 0);
    gather_kernel    <<<gather_blocks, 256>>>(hh, edges, off, dinv, b1, out1, N);

    // ---- layer 2 ----
    gemm_fp16s_kernel<<<gemm_blocks, 256>>>(out1, w2h, w2l, hh, N, 128);
    gather_kernel    <<<gather_blocks, 256>>>(hh, edges, off, dinv, b2, out, N);
}